// round 1
// baseline (speedup 1.0000x reference)
#include <cuda_runtime.h>

// Problem constants (match reference setup_inputs)
#define N_NODES 25000
#define N_EDGES 400000
#define F_DIM   128
#define S_DIM   256
#define L_DIM   64
#define ROUNDS  4

// ---------------- scratch (static __device__, no allocations) ----------------
__device__ float g_state[N_NODES * S_DIM];          // 25.6 MB
__device__ float g_P[N_NODES * 2 * S_DIM];          // 51.2 MB  (cols 0..255 = P_src part, 256..511 = P_dst part)
__device__ float g_Wcat[S_DIM * 2 * S_DIM];         // 512 KB   (rearranged W_msg[r])
__device__ int   g_cnt[N_NODES];
__device__ int   g_cur[N_NODES];
__device__ int   g_rowptr[N_NODES + 1];
__device__ int   g_esrc[N_EDGES];

// ---------------- CSR build (counting sort by dest) ----------------
__global__ void zero_counts_kernel() {
    int i = blockIdx.x * blockDim.x + threadIdx.x;
    if (i < N_NODES) { g_cnt[i] = 0; g_cur[i] = 0; }
}

__global__ void hist_kernel(const int* __restrict__ edge_index) {
    int e = blockIdx.x * blockDim.x + threadIdx.x;
    if (e < N_EDGES) {
        int d = edge_index[N_EDGES + e];   // dest row
        atomicAdd(&g_cnt[d], 1);
    }
}

// single-block exclusive scan of g_cnt -> g_rowptr
__global__ void scan_kernel() {
    __shared__ int partial[1024];
    const int CH = (N_NODES + 1023) / 1024;   // 25
    int t = threadIdx.x;
    int base = t * CH;
    int sum = 0;
    for (int i = 0; i < CH; i++) {
        int idx = base + i;
        if (idx < N_NODES) sum += g_cnt[idx];
    }
    partial[t] = sum;
    __syncthreads();
    if (t == 0) {
        int run = 0;
        for (int i = 0; i < 1024; i++) { int v = partial[i]; partial[i] = run; run += v; }
    }
    __syncthreads();
    int run = partial[t];
    for (int i = 0; i < CH; i++) {
        int idx = base + i;
        if (idx < N_NODES) { g_rowptr[idx] = run; run += g_cnt[idx]; }
    }
    if (base < N_NODES && base + CH >= N_NODES) g_rowptr[N_NODES] = run;
}

__global__ void fill_kernel(const int* __restrict__ edge_index) {
    int e = blockIdx.x * blockDim.x + threadIdx.x;
    if (e < N_EDGES) {
        int s = edge_index[e];
        int d = edge_index[N_EDGES + e];
        int pos = g_rowptr[d] + atomicAdd(&g_cur[d], 1);
        g_esrc[pos] = s;
    }
}

// ---------------- W rearrange: Wcat[k][j] = (j<S)? W[k][j] : W[S+k][j-S] ----------------
__global__ void wcat_kernel(const float* __restrict__ W) {
    int i = blockIdx.x * blockDim.x + threadIdx.x;
    if (i >= S_DIM * 2 * S_DIM) return;
    int k = i / (2 * S_DIM);
    int j = i % (2 * S_DIM);
    g_Wcat[i] = (j < S_DIM) ? W[k * S_DIM + j] : W[(S_DIM + k) * S_DIM + (j - S_DIM)];
}

// ---------------- generic tiled FFMA GEMM: C = act(A[M,K] @ B[K,N] + bias) ----------------
// BM=64, BN=64, BK=16, 256 threads, 4x4 per thread.
#define BM 64
#define BN 64
#define BK 16

__global__ __launch_bounds__(256) void gemm_kernel(
    const float* __restrict__ A, const float* __restrict__ B,
    const float* __restrict__ bias, float* __restrict__ C,
    int M, int N, int K, int do_relu)
{
    __shared__ float As[BK][BM];
    __shared__ float Bs[BK][BN];

    int tid  = threadIdx.x;
    int row0 = blockIdx.y * BM;
    int col0 = blockIdx.x * BN;
    int tx = tid % 16, ty = tid / 16;
    int tn0 = tx * 4, tm0 = ty * 4;

    float acc[4][4] = {};

    for (int k0 = 0; k0 < K; k0 += BK) {
        // A tile: 64 rows x 16 k, each thread loads float4 along K
        {
            int e  = tid * 4;
            int m  = e / BK;
            int kk = e % BK;
            int row = row0 + m;
            float4 v = make_float4(0.f, 0.f, 0.f, 0.f);
            if (row < M) v = *(const float4*)&A[(size_t)row * K + k0 + kk];
            As[kk + 0][m] = v.x; As[kk + 1][m] = v.y;
            As[kk + 2][m] = v.z; As[kk + 3][m] = v.w;
        }
        // B tile: 16 k x 64 cols, float4 along N
        {
            int e  = tid * 4;
            int kk = e / BN;
            int n  = e % BN;
            *(float4*)&Bs[kk][n] = *(const float4*)&B[(size_t)(k0 + kk) * N + col0 + n];
        }
        __syncthreads();

#pragma unroll
        for (int kk = 0; kk < BK; kk++) {
            float4 a4 = *(float4*)&As[kk][tm0];
            float4 b4 = *(float4*)&Bs[kk][tn0];
            float a[4] = {a4.x, a4.y, a4.z, a4.w};
            float b[4] = {b4.x, b4.y, b4.z, b4.w};
#pragma unroll
            for (int i = 0; i < 4; i++)
#pragma unroll
                for (int j = 0; j < 4; j++)
                    acc[i][j] += a[i] * b[j];
        }
        __syncthreads();
    }

    float bv[4] = {0.f, 0.f, 0.f, 0.f};
    if (bias) {
        float4 b4 = *(const float4*)&bias[col0 + tn0];
        bv[0] = b4.x; bv[1] = b4.y; bv[2] = b4.z; bv[3] = b4.w;
    }
#pragma unroll
    for (int i = 0; i < 4; i++) {
        int row = row0 + tm0 + i;
        if (row < M) {
            float4 o;
            o.x = acc[i][0] + bv[0];
            o.y = acc[i][1] + bv[1];
            o.z = acc[i][2] + bv[2];
            o.w = acc[i][3] + bv[3];
            if (do_relu) {
                o.x = fmaxf(o.x, 0.f); o.y = fmaxf(o.y, 0.f);
                o.z = fmaxf(o.z, 0.f); o.w = fmaxf(o.w, 0.f);
            }
            *(float4*)&C[(size_t)row * N + col0 + tn0] = o;
        }
    }
}

// ---------------- per-node aggregation: state[n] += sum_e relu(Psrc[src_e] + Pdst[n] + b) ----------------
// one warp per node; each lane owns 8 of the 256 columns (2x float4)
__global__ __launch_bounds__(256) void aggregate_kernel(const float* __restrict__ b_msg_r) {
    int warp = blockIdx.x * 8 + (threadIdx.x >> 5);
    if (warp >= N_NODES) return;
    int lane = threadIdx.x & 31;

    const float4* Pd = (const float4*)(g_P + (size_t)warp * (2 * S_DIM) + S_DIM);
    const float4* Bb = (const float4*)b_msg_r;

    float4 base0 = Pd[lane * 2 + 0];
    float4 base1 = Pd[lane * 2 + 1];
    float4 bb0 = Bb[lane * 2 + 0];
    float4 bb1 = Bb[lane * 2 + 1];
    base0.x += bb0.x; base0.y += bb0.y; base0.z += bb0.z; base0.w += bb0.w;
    base1.x += bb1.x; base1.y += bb1.y; base1.z += bb1.z; base1.w += bb1.w;

    float4 acc0 = make_float4(0.f, 0.f, 0.f, 0.f);
    float4 acc1 = make_float4(0.f, 0.f, 0.f, 0.f);

    int s = g_rowptr[warp];
    int e = g_rowptr[warp + 1];
    for (int i = s; i < e; i++) {
        int src = g_esrc[i];
        const float4* Ps = (const float4*)(g_P + (size_t)src * (2 * S_DIM));
        float4 v0 = Ps[lane * 2 + 0];
        float4 v1 = Ps[lane * 2 + 1];
        acc0.x += fmaxf(v0.x + base0.x, 0.f);
        acc0.y += fmaxf(v0.y + base0.y, 0.f);
        acc0.z += fmaxf(v0.z + base0.z, 0.f);
        acc0.w += fmaxf(v0.w + base0.w, 0.f);
        acc1.x += fmaxf(v1.x + base1.x, 0.f);
        acc1.y += fmaxf(v1.y + base1.y, 0.f);
        acc1.z += fmaxf(v1.z + base1.z, 0.f);
        acc1.w += fmaxf(v1.w + base1.w, 0.f);
    }

    float4* st = (float4*)(g_state + (size_t)warp * S_DIM);
    float4 s0 = st[lane * 2 + 0];
    float4 s1 = st[lane * 2 + 1];
    s0.x += acc0.x; s0.y += acc0.y; s0.z += acc0.z; s0.w += acc0.w;
    s1.x += acc1.x; s1.y += acc1.y; s1.z += acc1.z; s1.w += acc1.w;
    st[lane * 2 + 0] = s0;
    st[lane * 2 + 1] = s1;
}

// ---------------- launch ----------------
extern "C" void kernel_launch(void* const* d_in, const int* in_sizes, int n_in,
                              void* d_out, int out_size)
{
    const float* x        = (const float*)d_in[0];
    const int*   eidx     = (const int*)d_in[1];
    // d_in[2] = batch (unused by reference)
    const float* W_in     = (const float*)d_in[3];
    const float* b_in     = (const float*)d_in[4];
    const float* W_msg    = (const float*)d_in[5];   // [ROUNDS, 2S, S]
    const float* b_msg    = (const float*)d_in[6];   // [ROUNDS, S]
    const float* W_out    = (const float*)d_in[7];
    const float* b_out    = (const float*)d_in[8];
    float*       out      = (float*)d_out;

    float* state; cudaGetSymbolAddress((void**)&state, g_state);
    float* P;     cudaGetSymbolAddress((void**)&P,     g_P);
    float* Wcat;  cudaGetSymbolAddress((void**)&Wcat,  g_Wcat);

    // 1) CSR build (dest is identical every launch; rebuilt for determinism rules)
    zero_counts_kernel<<<(N_NODES + 255) / 256, 256>>>();
    hist_kernel<<<(N_EDGES + 255) / 256, 256>>>(eidx);
    scan_kernel<<<1, 1024>>>();
    fill_kernel<<<(N_EDGES + 255) / 256, 256>>>(eidx);

    // 2) input net: state = relu(x @ W_in + b_in)   [25000,128]@[128,256]
    {
        dim3 grid(S_DIM / BN, (N_NODES + BM - 1) / BM);
        gemm_kernel<<<grid, 256>>>(x, W_in, b_in, state, N_NODES, S_DIM, F_DIM, 1);
    }

    // 3) message rounds
    for (int r = 0; r < ROUNDS; r++) {
        // rearrange W_msg[r] (2S x S) into Wcat (S x 2S)
        wcat_kernel<<<(S_DIM * 2 * S_DIM + 255) / 256, 256>>>(W_msg + (size_t)r * 2 * S_DIM * S_DIM);
        // P = state @ Wcat   [25000,256]@[256,512]
        {
            dim3 grid((2 * S_DIM) / BN, (N_NODES + BM - 1) / BM);
            gemm_kernel<<<grid, 256>>>(state, Wcat, nullptr, P, N_NODES, 2 * S_DIM, S_DIM, 0);
        }
        // state[n] += sum over incoming edges of relu(P_src[src] + P_dst[n] + b_msg[r])
        aggregate_kernel<<<(N_NODES + 7) / 8, 256>>>(b_msg + (size_t)r * S_DIM);
    }

    // 4) output net: out = state @ W_out + b_out   [25000,256]@[256,64]
    {
        dim3 grid(L_DIM / BN, (N_NODES + BM - 1) / BM);
        gemm_kernel<<<grid, 256>>>(state, W_out, b_out, out, N_NODES, L_DIM, S_DIM, 0);
    }
}

// round 2
// speedup vs baseline: 1.9847x; 1.9847x over previous
#include <cuda_runtime.h>

// Problem constants (match reference setup_inputs)
#define N_NODES 25000
#define N_EDGES 400000
#define F_DIM   128
#define S_DIM   256
#define L_DIM   64
#define ROUNDS  4

// ---------------- scratch (static __device__, no allocations) ----------------
__device__ float g_state[N_NODES * S_DIM];          // 25.6 MB
__device__ float g_P[N_NODES * 2 * S_DIM];          // 51.2 MB
__device__ float g_Wcat[S_DIM * 2 * S_DIM];         // 512 KB
__device__ int   g_cnt[N_NODES];
__device__ int   g_cur[N_NODES];
__device__ int   g_rowptr[N_NODES + 1];
__device__ int   g_esrc[N_EDGES];

// ---------------- CSR build (counting sort by dest) ----------------
__global__ void zero_counts_kernel() {
    int i = blockIdx.x * blockDim.x + threadIdx.x;
    if (i < N_NODES) { g_cnt[i] = 0; g_cur[i] = 0; }
}

__global__ void hist_kernel(const int* __restrict__ edge_index) {
    int e = blockIdx.x * blockDim.x + threadIdx.x;
    if (e < N_EDGES) {
        int d = edge_index[N_EDGES + e];
        atomicAdd(&g_cnt[d], 1);
    }
}

// single-block exclusive scan of g_cnt -> g_rowptr (shfl-based, 1024 threads)
__global__ void scan_kernel() {
    __shared__ int warp_tot[32];
    const int CH = (N_NODES + 1023) / 1024;   // 25
    int t = threadIdx.x;
    int lane = t & 31, wid = t >> 5;
    int base = t * CH;
    int sum = 0;
#pragma unroll
    for (int i = 0; i < CH; i++) {
        int idx = base + i;
        if (idx < N_NODES) sum += g_cnt[idx];
    }
    // inclusive warp scan
    int v = sum;
#pragma unroll
    for (int off = 1; off < 32; off <<= 1) {
        int n = __shfl_up_sync(0xffffffff, v, off);
        if (lane >= off) v += n;
    }
    if (lane == 31) warp_tot[wid] = v;
    __syncthreads();
    if (wid == 0) {
        int w = warp_tot[lane];
#pragma unroll
        for (int off = 1; off < 32; off <<= 1) {
            int n = __shfl_up_sync(0xffffffff, w, off);
            if (lane >= off) w += n;
        }
        warp_tot[lane] = w;
    }
    __syncthreads();
    int excl = v - sum + (wid > 0 ? warp_tot[wid - 1] : 0);  // exclusive prefix of this thread
    int run = excl;
#pragma unroll
    for (int i = 0; i < CH; i++) {
        int idx = base + i;
        if (idx < N_NODES) { g_rowptr[idx] = run; run += g_cnt[idx]; }
    }
    if (t == 1023) g_rowptr[N_NODES] = run;
}

__global__ void fill_kernel(const int* __restrict__ edge_index) {
    int e = blockIdx.x * blockDim.x + threadIdx.x;
    if (e < N_EDGES) {
        int s = edge_index[e];
        int d = edge_index[N_EDGES + e];
        int pos = g_rowptr[d] + atomicAdd(&g_cur[d], 1);
        g_esrc[pos] = s;
    }
}

// ---------------- W rearrange: Wcat[k][j] = (j<S)? W[k][j] : W[S+k][j-S] ----------------
__global__ void wcat_kernel(const float* __restrict__ W) {
    int i = blockIdx.x * blockDim.x + threadIdx.x;
    if (i >= S_DIM * 2 * S_DIM) return;
    int k = i / (2 * S_DIM);
    int j = i % (2 * S_DIM);
    g_Wcat[i] = (j < S_DIM) ? W[k * S_DIM + j] : W[(S_DIM + k) * S_DIM + (j - S_DIM)];
}

// ---------------- TF32 tensor-core GEMM: C = act(A[M,K] @ B[K,N] + bias) ----------------
// BM=128, BN=128, BK=32, 256 threads (8 warps), warp tile 64x32 via m16n8k8 mma.
#define TBM 128
#define TBN 128
#define TBK 32
#define A_PAD 133
#define B_PAD 132

__device__ __forceinline__ unsigned f2tf32(float f) {
    unsigned r;
    asm("cvt.rna.tf32.f32 %0, %1;" : "=r"(r) : "f"(f));
    return r;
}

__global__ __launch_bounds__(256) void gemm_tf32_kernel(
    const float* __restrict__ A, const float* __restrict__ B,
    const float* __restrict__ bias, float* __restrict__ C,
    int M, int N, int K, int do_relu)
{
    __shared__ unsigned As[TBK][A_PAD];   // [k][m]
    __shared__ unsigned Bs[TBK][B_PAD];   // [k][n]

    int tid  = threadIdx.x;
    int lane = tid & 31;
    int wid  = tid >> 5;
    int warp_m = wid & 1;          // 2 along m
    int warp_n = wid >> 1;         // 4 along n
    int m_warp = warp_m * 64;
    int n_warp = warp_n * 32;
    int g   = lane >> 2;
    int tig = lane & 3;

    int row_blk = blockIdx.y * TBM;
    int col_blk = blockIdx.x * TBN;

    float c[4][4][4];               // [mt][nt][4]
#pragma unroll
    for (int mt = 0; mt < 4; mt++)
#pragma unroll
        for (int nt = 0; nt < 4; nt++)
#pragma unroll
            for (int i = 0; i < 4; i++) c[mt][nt][i] = 0.f;

    // global-load index precompute
    int a_kt  = tid & 7;            // 8 float4 per 32-wide k row
    int a_row = tid >> 3;           // 32 rows per pass, 4 passes
    int b_nt  = tid & 31;           // 32 float4 per 128-wide n row
    int b_kr  = tid >> 5;           // 8 k-rows per pass, 4 passes

    for (int k0 = 0; k0 < K; k0 += TBK) {
        // A tile: 128 rows x 32 k, store transposed As[k][m]
#pragma unroll
        for (int p = 0; p < 4; p++) {
            int row = p * 32 + a_row;
            int grow = row_blk + row;
            float4 v = make_float4(0.f, 0.f, 0.f, 0.f);
            if (grow < M) v = *(const float4*)&A[(size_t)grow * K + k0 + a_kt * 4];
            As[a_kt * 4 + 0][row] = f2tf32(v.x);
            As[a_kt * 4 + 1][row] = f2tf32(v.y);
            As[a_kt * 4 + 2][row] = f2tf32(v.z);
            As[a_kt * 4 + 3][row] = f2tf32(v.w);
        }
        // B tile: 32 k x 128 n
#pragma unroll
        for (int p = 0; p < 4; p++) {
            int kk = p * 8 + b_kr;
            float4 v = *(const float4*)&B[(size_t)(k0 + kk) * N + col_blk + b_nt * 4];
            uint4 w;
            w.x = f2tf32(v.x); w.y = f2tf32(v.y);
            w.z = f2tf32(v.z); w.w = f2tf32(v.w);
            *(uint4*)&Bs[kk][b_nt * 4] = w;
        }
        __syncthreads();

#pragma unroll
        for (int ks = 0; ks < TBK; ks += 8) {
            unsigned af[4][4], bf[4][2];
#pragma unroll
            for (int mt = 0; mt < 4; mt++) {
                int mb = m_warp + mt * 16;
                af[mt][0] = As[ks + tig][mb + g];
                af[mt][1] = As[ks + tig][mb + g + 8];
                af[mt][2] = As[ks + tig + 4][mb + g];
                af[mt][3] = As[ks + tig + 4][mb + g + 8];
            }
#pragma unroll
            for (int nt = 0; nt < 4; nt++) {
                int nb = n_warp + nt * 8;
                bf[nt][0] = Bs[ks + tig][nb + g];
                bf[nt][1] = Bs[ks + tig + 4][nb + g];
            }
#pragma unroll
            for (int mt = 0; mt < 4; mt++)
#pragma unroll
                for (int nt = 0; nt < 4; nt++) {
                    asm volatile(
                        "mma.sync.aligned.m16n8k8.row.col.f32.tf32.tf32.f32 "
                        "{%0,%1,%2,%3}, {%4,%5,%6,%7}, {%8,%9}, {%0,%1,%2,%3};"
                        : "+f"(c[mt][nt][0]), "+f"(c[mt][nt][1]),
                          "+f"(c[mt][nt][2]), "+f"(c[mt][nt][3])
                        : "r"(af[mt][0]), "r"(af[mt][1]), "r"(af[mt][2]), "r"(af[mt][3]),
                          "r"(bf[nt][0]), "r"(bf[nt][1]));
                }
        }
        __syncthreads();
    }

    // epilogue
#pragma unroll
    for (int mt = 0; mt < 4; mt++) {
#pragma unroll
        for (int nt = 0; nt < 4; nt++) {
            int col = col_blk + n_warp + nt * 8 + tig * 2;
            float bv0 = bias ? bias[col] : 0.f;
            float bv1 = bias ? bias[col + 1] : 0.f;
            int r0 = row_blk + m_warp + mt * 16 + g;
            int r1 = r0 + 8;
            float2 o0, o1;
            o0.x = c[mt][nt][0] + bv0; o0.y = c[mt][nt][1] + bv1;
            o1.x = c[mt][nt][2] + bv0; o1.y = c[mt][nt][3] + bv1;
            if (do_relu) {
                o0.x = fmaxf(o0.x, 0.f); o0.y = fmaxf(o0.y, 0.f);
                o1.x = fmaxf(o1.x, 0.f); o1.y = fmaxf(o1.y, 0.f);
            }
            if (r0 < M) *(float2*)&C[(size_t)r0 * N + col] = o0;
            if (r1 < M) *(float2*)&C[(size_t)r1 * N + col] = o1;
        }
    }
}

// ---------------- fp32 FFMA GEMM (kept for the small N=64 output GEMM) ----------------
#define BM 64
#define BN 64
#define BK 16

__global__ __launch_bounds__(256) void gemm_kernel(
    const float* __restrict__ A, const float* __restrict__ B,
    const float* __restrict__ bias, float* __restrict__ C,
    int M, int N, int K, int do_relu)
{
    __shared__ float As[BK][BM];
    __shared__ float Bs[BK][BN];

    int tid  = threadIdx.x;
    int row0 = blockIdx.y * BM;
    int col0 = blockIdx.x * BN;
    int tx = tid % 16, ty = tid / 16;
    int tn0 = tx * 4, tm0 = ty * 4;

    float acc[4][4] = {};

    for (int k0 = 0; k0 < K; k0 += BK) {
        {
            int e  = tid * 4;
            int m  = e / BK;
            int kk = e % BK;
            int row = row0 + m;
            float4 v = make_float4(0.f, 0.f, 0.f, 0.f);
            if (row < M) v = *(const float4*)&A[(size_t)row * K + k0 + kk];
            As[kk + 0][m] = v.x; As[kk + 1][m] = v.y;
            As[kk + 2][m] = v.z; As[kk + 3][m] = v.w;
        }
        {
            int e  = tid * 4;
            int kk = e / BN;
            int n  = e % BN;
            *(float4*)&Bs[kk][n] = *(const float4*)&B[(size_t)(k0 + kk) * N + col0 + n];
        }
        __syncthreads();

#pragma unroll
        for (int kk = 0; kk < BK; kk++) {
            float4 a4 = *(float4*)&As[kk][tm0];
            float4 b4 = *(float4*)&Bs[kk][tn0];
            float a[4] = {a4.x, a4.y, a4.z, a4.w};
            float b[4] = {b4.x, b4.y, b4.z, b4.w};
#pragma unroll
            for (int i = 0; i < 4; i++)
#pragma unroll
                for (int j = 0; j < 4; j++)
                    acc[i][j] += a[i] * b[j];
        }
        __syncthreads();
    }

    float bv[4] = {0.f, 0.f, 0.f, 0.f};
    if (bias) {
        float4 b4 = *(const float4*)&bias[col0 + tn0];
        bv[0] = b4.x; bv[1] = b4.y; bv[2] = b4.z; bv[3] = b4.w;
    }
#pragma unroll
    for (int i = 0; i < 4; i++) {
        int row = row0 + tm0 + i;
        if (row < M) {
            float4 o;
            o.x = acc[i][0] + bv[0];
            o.y = acc[i][1] + bv[1];
            o.z = acc[i][2] + bv[2];
            o.w = acc[i][3] + bv[3];
            if (do_relu) {
                o.x = fmaxf(o.x, 0.f); o.y = fmaxf(o.y, 0.f);
                o.z = fmaxf(o.z, 0.f); o.w = fmaxf(o.w, 0.f);
            }
            *(float4*)&C[(size_t)row * N + col0 + tn0] = o;
        }
    }
}

// ---------------- per-node aggregation ----------------
// state[n] += sum_e relu(Psrc[src_e] + Pdst[n] + b); one warp per node
__global__ __launch_bounds__(256) void aggregate_kernel(const float* __restrict__ b_msg_r) {
    int warp = blockIdx.x * 8 + (threadIdx.x >> 5);
    if (warp >= N_NODES) return;
    int lane = threadIdx.x & 31;

    const float4* Pd = (const float4*)(g_P + (size_t)warp * (2 * S_DIM) + S_DIM);
    const float4* Bb = (const float4*)b_msg_r;

    float4 base0 = Pd[lane * 2 + 0];
    float4 base1 = Pd[lane * 2 + 1];
    float4 bb0 = Bb[lane * 2 + 0];
    float4 bb1 = Bb[lane * 2 + 1];
    base0.x += bb0.x; base0.y += bb0.y; base0.z += bb0.z; base0.w += bb0.w;
    base1.x += bb1.x; base1.y += bb1.y; base1.z += bb1.z; base1.w += bb1.w;

    float4 acc0 = make_float4(0.f, 0.f, 0.f, 0.f);
    float4 acc1 = make_float4(0.f, 0.f, 0.f, 0.f);

    int s = g_rowptr[warp];
    int e = g_rowptr[warp + 1];
    int src_next = (s < e) ? g_esrc[s] : 0;
    for (int i = s; i < e; i++) {
        int src = src_next;
        if (i + 1 < e) src_next = g_esrc[i + 1];
        const float4* Ps = (const float4*)(g_P + (size_t)src * (2 * S_DIM));
        float4 v0 = Ps[lane * 2 + 0];
        float4 v1 = Ps[lane * 2 + 1];
        acc0.x += fmaxf(v0.x + base0.x, 0.f);
        acc0.y += fmaxf(v0.y + base0.y, 0.f);
        acc0.z += fmaxf(v0.z + base0.z, 0.f);
        acc0.w += fmaxf(v0.w + base0.w, 0.f);
        acc1.x += fmaxf(v1.x + base1.x, 0.f);
        acc1.y += fmaxf(v1.y + base1.y, 0.f);
        acc1.z += fmaxf(v1.z + base1.z, 0.f);
        acc1.w += fmaxf(v1.w + base1.w, 0.f);
    }

    float4* st = (float4*)(g_state + (size_t)warp * S_DIM);
    float4 s0 = st[lane * 2 + 0];
    float4 s1 = st[lane * 2 + 1];
    s0.x += acc0.x; s0.y += acc0.y; s0.z += acc0.z; s0.w += acc0.w;
    s1.x += acc1.x; s1.y += acc1.y; s1.z += acc1.z; s1.w += acc1.w;
    st[lane * 2 + 0] = s0;
    st[lane * 2 + 1] = s1;
}

// ---------------- launch ----------------
extern "C" void kernel_launch(void* const* d_in, const int* in_sizes, int n_in,
                              void* d_out, int out_size)
{
    const float* x        = (const float*)d_in[0];
    const int*   eidx     = (const int*)d_in[1];
    // d_in[2] = batch (unused by reference)
    const float* W_in     = (const float*)d_in[3];
    const float* b_in     = (const float*)d_in[4];
    const float* W_msg    = (const float*)d_in[5];   // [ROUNDS, 2S, S]
    const float* b_msg    = (const float*)d_in[6];   // [ROUNDS, S]
    const float* W_out    = (const float*)d_in[7];
    const float* b_out    = (const float*)d_in[8];
    float*       out      = (float*)d_out;

    float* state; cudaGetSymbolAddress((void**)&state, g_state);
    float* P;     cudaGetSymbolAddress((void**)&P,     g_P);
    float* Wcat;  cudaGetSymbolAddress((void**)&Wcat,  g_Wcat);

    // 1) CSR build
    zero_counts_kernel<<<(N_NODES + 255) / 256, 256>>>();
    hist_kernel<<<(N_EDGES + 255) / 256, 256>>>(eidx);
    scan_kernel<<<1, 1024>>>();
    fill_kernel<<<(N_EDGES + 255) / 256, 256>>>(eidx);

    // 2) input net: state = relu(x @ W_in + b_in)   [25000,128]@[128,256]
    {
        dim3 grid(S_DIM / TBN, (N_NODES + TBM - 1) / TBM);
        gemm_tf32_kernel<<<grid, 256>>>(x, W_in, b_in, state, N_NODES, S_DIM, F_DIM, 1);
    }

    // 3) message rounds
    for (int r = 0; r < ROUNDS; r++) {
        wcat_kernel<<<(S_DIM * 2 * S_DIM + 255) / 256, 256>>>(W_msg + (size_t)r * 2 * S_DIM * S_DIM);
        {
            dim3 grid((2 * S_DIM) / TBN, (N_NODES + TBM - 1) / TBM);
            gemm_tf32_kernel<<<grid, 256>>>(state, Wcat, nullptr, P, N_NODES, 2 * S_DIM, S_DIM, 0);
        }
        aggregate_kernel<<<(N_NODES + 7) / 8, 256>>>(b_msg + (size_t)r * S_DIM);
    }

    // 4) output net: out = state @ W_out + b_out   [25000,256]@[256,64]  (fp32 path)
    {
        dim3 grid(L_DIM / BN, (N_NODES + BM - 1) / BM);
        gemm_kernel<<<grid, 256>>>(state, W_out, b_out, out, N_NODES, L_DIM, S_DIM, 0);
    }
}

// round 3
// speedup vs baseline: 2.0533x; 1.0345x over previous
#include <cuda_runtime.h>

// Problem constants (match reference setup_inputs)
#define N_NODES 25000
#define N_EDGES 400000
#define F_DIM   128
#define S_DIM   256
#define L_DIM   64
#define ROUNDS  4

// ---------------- scratch (static __device__, no allocations) ----------------
__device__ float g_state[N_NODES * S_DIM];                 // 25.6 MB
__device__ float g_P[N_NODES * 2 * S_DIM];                 // 51.2 MB
__device__ float g_Wcat[ROUNDS * S_DIM * 2 * S_DIM];       // 2 MB (all rounds)
__device__ int   g_cnt[N_NODES];
__device__ int   g_cur[N_NODES];
__device__ int   g_rowptr[N_NODES + 1];
__device__ int   g_esrc[N_EDGES];

// ---------------- CSR build (counting sort by dest) ----------------
__global__ void zero_counts_kernel() {
    int i = blockIdx.x * blockDim.x + threadIdx.x;
    if (i < N_NODES) { g_cnt[i] = 0; g_cur[i] = 0; }
}

__global__ void hist_kernel(const int* __restrict__ edge_index) {
    int e = blockIdx.x * blockDim.x + threadIdx.x;
    if (e < N_EDGES) {
        int d = edge_index[N_EDGES + e];
        atomicAdd(&g_cnt[d], 1);
    }
}

// single-block exclusive scan of g_cnt -> g_rowptr (shfl-based, 1024 threads)
__global__ void scan_kernel() {
    __shared__ int warp_tot[32];
    const int CH = (N_NODES + 1023) / 1024;   // 25
    int t = threadIdx.x;
    int lane = t & 31, wid = t >> 5;
    int base = t * CH;
    int sum = 0;
#pragma unroll
    for (int i = 0; i < CH; i++) {
        int idx = base + i;
        if (idx < N_NODES) sum += g_cnt[idx];
    }
    int v = sum;
#pragma unroll
    for (int off = 1; off < 32; off <<= 1) {
        int n = __shfl_up_sync(0xffffffff, v, off);
        if (lane >= off) v += n;
    }
    if (lane == 31) warp_tot[wid] = v;
    __syncthreads();
    if (wid == 0) {
        int w = warp_tot[lane];
#pragma unroll
        for (int off = 1; off < 32; off <<= 1) {
            int n = __shfl_up_sync(0xffffffff, w, off);
            if (lane >= off) w += n;
        }
        warp_tot[lane] = w;
    }
    __syncthreads();
    int excl = v - sum + (wid > 0 ? warp_tot[wid - 1] : 0);
    int run = excl;
#pragma unroll
    for (int i = 0; i < CH; i++) {
        int idx = base + i;
        if (idx < N_NODES) { g_rowptr[idx] = run; run += g_cnt[idx]; }
    }
    if (t == 1023) g_rowptr[N_NODES] = run;
}

__global__ void fill_kernel(const int* __restrict__ edge_index) {
    int e = blockIdx.x * blockDim.x + threadIdx.x;
    if (e < N_EDGES) {
        int s = edge_index[e];
        int d = edge_index[N_EDGES + e];
        int pos = g_rowptr[d] + atomicAdd(&g_cur[d], 1);
        g_esrc[pos] = s;
    }
}

// ---------------- W rearrange for ALL rounds in one launch ----------------
// Wcat[r][k][j] = (j<S)? W[r][k][j] : W[r][S+k][j-S]
__global__ void wcat_kernel(const float* __restrict__ W) {
    int i = blockIdx.x * blockDim.x + threadIdx.x;
    if (i >= ROUNDS * S_DIM * 2 * S_DIM) return;
    int r = i / (S_DIM * 2 * S_DIM);
    int rem = i % (S_DIM * 2 * S_DIM);
    int k = rem / (2 * S_DIM);
    int j = rem % (2 * S_DIM);
    const float* Wr = W + (size_t)r * 2 * S_DIM * S_DIM;
    g_Wcat[i] = (j < S_DIM) ? Wr[k * S_DIM + j] : Wr[(S_DIM + k) * S_DIM + (j - S_DIM)];
}

// ---------------- TF32 tensor-core GEMM, double-buffered ----------------
// BM=128, BN=128, BK=32, 256 threads (8 warps), warp tile 64x32 via m16n8k8.
#define TBM 128
#define TBN 128
#define TBK 32
#define A_PAD 133
#define B_PAD 132
#define A_BUF_ELEMS (TBK * A_PAD)
#define B_BUF_ELEMS (TBK * B_PAD)
#define SMEM_BYTES ((2 * A_BUF_ELEMS + 2 * B_BUF_ELEMS) * 4)

__device__ __forceinline__ unsigned f2tf32(float f) {
    unsigned r;
    asm("cvt.rna.tf32.f32 %0, %1;" : "=r"(r) : "f"(f));
    return r;
}

__global__ __launch_bounds__(256, 2) void gemm_tf32_kernel(
    const float* __restrict__ A, const float* __restrict__ B,
    const float* __restrict__ bias, float* __restrict__ C,
    int M, int N, int K, int do_relu)
{
    extern __shared__ unsigned smem[];
    unsigned* As = smem;                       // [2][TBK][A_PAD]
    unsigned* Bs = smem + 2 * A_BUF_ELEMS;     // [2][TBK][B_PAD]

    int tid  = threadIdx.x;
    int lane = tid & 31;
    int wid  = tid >> 5;
    int warp_m = wid & 1;
    int warp_n = wid >> 1;
    int m_warp = warp_m * 64;
    int n_warp = warp_n * 32;
    int g   = lane >> 2;
    int tig = lane & 3;

    int row_blk = blockIdx.y * TBM;
    int col_blk = blockIdx.x * TBN;

    float c[4][4][4];
#pragma unroll
    for (int mt = 0; mt < 4; mt++)
#pragma unroll
        for (int nt = 0; nt < 4; nt++)
#pragma unroll
            for (int i = 0; i < 4; i++) c[mt][nt][i] = 0.f;

    int a_kt  = tid & 7;            // 8 float4 per 32-wide k row
    int a_row = tid >> 3;           // 32 rows per pass, 4 passes
    int b_nt  = tid & 31;           // 32 float4 per 128-wide n row
    int b_kr  = tid >> 5;           // 8 k-rows per pass, 4 passes

    int nk = K / TBK;
    float4 av[4], bv4[4];

    // prologue: load tile 0
#pragma unroll
    for (int p = 0; p < 4; p++) {
        int grow = row_blk + p * 32 + a_row;
        av[p] = make_float4(0.f, 0.f, 0.f, 0.f);
        if (grow < M) av[p] = *(const float4*)&A[(size_t)grow * K + a_kt * 4];
        bv4[p] = *(const float4*)&B[(size_t)(p * 8 + b_kr) * N + col_blk + b_nt * 4];
    }

    for (int t = 0; t < nk; t++) {
        int cur = t & 1;
        unsigned* Ac = As + cur * A_BUF_ELEMS;
        unsigned* Bc = Bs + cur * B_BUF_ELEMS;

        // store staged regs for tile t into cur buffer
#pragma unroll
        for (int p = 0; p < 4; p++) {
            int row = p * 32 + a_row;
            Ac[(a_kt * 4 + 0) * A_PAD + row] = f2tf32(av[p].x);
            Ac[(a_kt * 4 + 1) * A_PAD + row] = f2tf32(av[p].y);
            Ac[(a_kt * 4 + 2) * A_PAD + row] = f2tf32(av[p].z);
            Ac[(a_kt * 4 + 3) * A_PAD + row] = f2tf32(av[p].w);
            int kk = p * 8 + b_kr;
            uint4 w;
            w.x = f2tf32(bv4[p].x); w.y = f2tf32(bv4[p].y);
            w.z = f2tf32(bv4[p].z); w.w = f2tf32(bv4[p].w);
            *(uint4*)&Bc[kk * B_PAD + b_nt * 4] = w;
        }
        __syncthreads();

        // issue global loads for tile t+1 (overlap with mma below)
        if (t + 1 < nk) {
            int k0 = (t + 1) * TBK;
#pragma unroll
            for (int p = 0; p < 4; p++) {
                int grow = row_blk + p * 32 + a_row;
                av[p] = make_float4(0.f, 0.f, 0.f, 0.f);
                if (grow < M) av[p] = *(const float4*)&A[(size_t)grow * K + k0 + a_kt * 4];
                bv4[p] = *(const float4*)&B[(size_t)(k0 + p * 8 + b_kr) * N + col_blk + b_nt * 4];
            }
        }

        // mma over tile t
#pragma unroll
        for (int ks = 0; ks < TBK; ks += 8) {
            unsigned af[4][4], bf[4][2];
#pragma unroll
            for (int mt = 0; mt < 4; mt++) {
                int mb = m_warp + mt * 16;
                af[mt][0] = Ac[(ks + tig) * A_PAD + mb + g];
                af[mt][1] = Ac[(ks + tig) * A_PAD + mb + g + 8];
                af[mt][2] = Ac[(ks + tig + 4) * A_PAD + mb + g];
                af[mt][3] = Ac[(ks + tig + 4) * A_PAD + mb + g + 8];
            }
#pragma unroll
            for (int nt = 0; nt < 4; nt++) {
                int nb = n_warp + nt * 8;
                bf[nt][0] = Bc[(ks + tig) * B_PAD + nb + g];
                bf[nt][1] = Bc[(ks + tig + 4) * B_PAD + nb + g];
            }
#pragma unroll
            for (int mt = 0; mt < 4; mt++)
#pragma unroll
                for (int nt = 0; nt < 4; nt++) {
                    asm volatile(
                        "mma.sync.aligned.m16n8k8.row.col.f32.tf32.tf32.f32 "
                        "{%0,%1,%2,%3}, {%4,%5,%6,%7}, {%8,%9}, {%0,%1,%2,%3};"
                        : "+f"(c[mt][nt][0]), "+f"(c[mt][nt][1]),
                          "+f"(c[mt][nt][2]), "+f"(c[mt][nt][3])
                        : "r"(af[mt][0]), "r"(af[mt][1]), "r"(af[mt][2]), "r"(af[mt][3]),
                          "r"(bf[nt][0]), "r"(bf[nt][1]));
                }
        }
        __syncthreads();
    }

    // epilogue
#pragma unroll
    for (int mt = 0; mt < 4; mt++) {
#pragma unroll
        for (int nt = 0; nt < 4; nt++) {
            int col = col_blk + n_warp + nt * 8 + tig * 2;
            float bv0 = bias ? bias[col] : 0.f;
            float bv1 = bias ? bias[col + 1] : 0.f;
            int r0 = row_blk + m_warp + mt * 16 + g;
            int r1 = r0 + 8;
            float2 o0, o1;
            o0.x = c[mt][nt][0] + bv0; o0.y = c[mt][nt][1] + bv1;
            o1.x = c[mt][nt][2] + bv0; o1.y = c[mt][nt][3] + bv1;
            if (do_relu) {
                o0.x = fmaxf(o0.x, 0.f); o0.y = fmaxf(o0.y, 0.f);
                o1.x = fmaxf(o1.x, 0.f); o1.y = fmaxf(o1.y, 0.f);
            }
            if (r0 < M) *(float2*)&C[(size_t)r0 * N + col] = o0;
            if (r1 < M) *(float2*)&C[(size_t)r1 * N + col] = o1;
        }
    }
}

// ---------------- fp32 FFMA GEMM (small N=64 output GEMM) ----------------
#define BM 64
#define BN 64
#define BK 16

__global__ __launch_bounds__(256) void gemm_kernel(
    const float* __restrict__ A, const float* __restrict__ B,
    const float* __restrict__ bias, float* __restrict__ C,
    int M, int N, int K, int do_relu)
{
    __shared__ float As[BK][BM];
    __shared__ float Bs[BK][BN];

    int tid  = threadIdx.x;
    int row0 = blockIdx.y * BM;
    int col0 = blockIdx.x * BN;
    int tx = tid % 16, ty = tid / 16;
    int tn0 = tx * 4, tm0 = ty * 4;

    float acc[4][4] = {};

    for (int k0 = 0; k0 < K; k0 += BK) {
        {
            int e  = tid * 4;
            int m  = e / BK;
            int kk = e % BK;
            int row = row0 + m;
            float4 v = make_float4(0.f, 0.f, 0.f, 0.f);
            if (row < M) v = *(const float4*)&A[(size_t)row * K + k0 + kk];
            As[kk + 0][m] = v.x; As[kk + 1][m] = v.y;
            As[kk + 2][m] = v.z; As[kk + 3][m] = v.w;
        }
        {
            int e  = tid * 4;
            int kk = e / BN;
            int n  = e % BN;
            *(float4*)&Bs[kk][n] = *(const float4*)&B[(size_t)(k0 + kk) * N + col0 + n];
        }
        __syncthreads();

#pragma unroll
        for (int kk = 0; kk < BK; kk++) {
            float4 a4 = *(float4*)&As[kk][tm0];
            float4 b4 = *(float4*)&Bs[kk][tn0];
            float a[4] = {a4.x, a4.y, a4.z, a4.w};
            float b[4] = {b4.x, b4.y, b4.z, b4.w};
#pragma unroll
            for (int i = 0; i < 4; i++)
#pragma unroll
                for (int j = 0; j < 4; j++)
                    acc[i][j] += a[i] * b[j];
        }
        __syncthreads();
    }

    float bv[4] = {0.f, 0.f, 0.f, 0.f};
    if (bias) {
        float4 b4 = *(const float4*)&bias[col0 + tn0];
        bv[0] = b4.x; bv[1] = b4.y; bv[2] = b4.z; bv[3] = b4.w;
    }
#pragma unroll
    for (int i = 0; i < 4; i++) {
        int row = row0 + tm0 + i;
        if (row < M) {
            float4 o;
            o.x = acc[i][0] + bv[0];
            o.y = acc[i][1] + bv[1];
            o.z = acc[i][2] + bv[2];
            o.w = acc[i][3] + bv[3];
            if (do_relu) {
                o.x = fmaxf(o.x, 0.f); o.y = fmaxf(o.y, 0.f);
                o.z = fmaxf(o.z, 0.f); o.w = fmaxf(o.w, 0.f);
            }
            *(float4*)&C[(size_t)row * N + col0 + tn0] = o;
        }
    }
}

// ---------------- per-node aggregation, edge loop unrolled x2 ----------------
// state[n] += sum_e relu(Psrc[src_e] + Pdst[n] + b); one warp per node
__global__ __launch_bounds__(256) void aggregate_kernel(const float* __restrict__ b_msg_r) {
    int warp = blockIdx.x * 8 + (threadIdx.x >> 5);
    if (warp >= N_NODES) return;
    int lane = threadIdx.x & 31;

    const float4* Pd = (const float4*)(g_P + (size_t)warp * (2 * S_DIM) + S_DIM);
    const float4* Bb = (const float4*)b_msg_r;

    float4 base0 = Pd[lane * 2 + 0];
    float4 base1 = Pd[lane * 2 + 1];
    float4 bb0 = Bb[lane * 2 + 0];
    float4 bb1 = Bb[lane * 2 + 1];
    base0.x += bb0.x; base0.y += bb0.y; base0.z += bb0.z; base0.w += bb0.w;
    base1.x += bb1.x; base1.y += bb1.y; base1.z += bb1.z; base1.w += bb1.w;

    float4 acc0 = make_float4(0.f, 0.f, 0.f, 0.f);
    float4 acc1 = make_float4(0.f, 0.f, 0.f, 0.f);

    int s = g_rowptr[warp];
    int e = g_rowptr[warp + 1];
    int i = s;
    for (; i + 2 <= e; i += 2) {
        int s0 = g_esrc[i];
        int s1 = g_esrc[i + 1];
        const float4* P0 = (const float4*)(g_P + (size_t)s0 * (2 * S_DIM));
        const float4* P1 = (const float4*)(g_P + (size_t)s1 * (2 * S_DIM));
        float4 u0 = P0[lane * 2 + 0];
        float4 u1 = P0[lane * 2 + 1];
        float4 w0 = P1[lane * 2 + 0];
        float4 w1 = P1[lane * 2 + 1];
        acc0.x += fmaxf(u0.x + base0.x, 0.f) + fmaxf(w0.x + base0.x, 0.f);
        acc0.y += fmaxf(u0.y + base0.y, 0.f) + fmaxf(w0.y + base0.y, 0.f);
        acc0.z += fmaxf(u0.z + base0.z, 0.f) + fmaxf(w0.z + base0.z, 0.f);
        acc0.w += fmaxf(u0.w + base0.w, 0.f) + fmaxf(w0.w + base0.w, 0.f);
        acc1.x += fmaxf(u1.x + base1.x, 0.f) + fmaxf(w1.x + base1.x, 0.f);
        acc1.y += fmaxf(u1.y + base1.y, 0.f) + fmaxf(w1.y + base1.y, 0.f);
        acc1.z += fmaxf(u1.z + base1.z, 0.f) + fmaxf(w1.z + base1.z, 0.f);
        acc1.w += fmaxf(u1.w + base1.w, 0.f) + fmaxf(w1.w + base1.w, 0.f);
    }
    if (i < e) {
        int s0 = g_esrc[i];
        const float4* P0 = (const float4*)(g_P + (size_t)s0 * (2 * S_DIM));
        float4 u0 = P0[lane * 2 + 0];
        float4 u1 = P0[lane * 2 + 1];
        acc0.x += fmaxf(u0.x + base0.x, 0.f);
        acc0.y += fmaxf(u0.y + base0.y, 0.f);
        acc0.z += fmaxf(u0.z + base0.z, 0.f);
        acc0.w += fmaxf(u0.w + base0.w, 0.f);
        acc1.x += fmaxf(u1.x + base1.x, 0.f);
        acc1.y += fmaxf(u1.y + base1.y, 0.f);
        acc1.z += fmaxf(u1.z + base1.z, 0.f);
        acc1.w += fmaxf(u1.w + base1.w, 0.f);
    }

    float4* st = (float4*)(g_state + (size_t)warp * S_DIM);
    float4 s0 = st[lane * 2 + 0];
    float4 s1 = st[lane * 2 + 1];
    s0.x += acc0.x; s0.y += acc0.y; s0.z += acc0.z; s0.w += acc0.w;
    s1.x += acc1.x; s1.y += acc1.y; s1.z += acc1.z; s1.w += acc1.w;
    st[lane * 2 + 0] = s0;
    st[lane * 2 + 1] = s1;
}

// ---------------- launch ----------------
extern "C" void kernel_launch(void* const* d_in, const int* in_sizes, int n_in,
                              void* d_out, int out_size)
{
    const float* x        = (const float*)d_in[0];
    const int*   eidx     = (const int*)d_in[1];
    // d_in[2] = batch (unused by reference)
    const float* W_in     = (const float*)d_in[3];
    const float* b_in     = (const float*)d_in[4];
    const float* W_msg    = (const float*)d_in[5];   // [ROUNDS, 2S, S]
    const float* b_msg    = (const float*)d_in[6];   // [ROUNDS, S]
    const float* W_out    = (const float*)d_in[7];
    const float* b_out    = (const float*)d_in[8];
    float*       out      = (float*)d_out;

    float* state; cudaGetSymbolAddress((void**)&state, g_state);
    float* P;     cudaGetSymbolAddress((void**)&P,     g_P);
    float* Wcat;  cudaGetSymbolAddress((void**)&Wcat,  g_Wcat);

    cudaFuncSetAttribute(gemm_tf32_kernel,
                         cudaFuncAttributeMaxDynamicSharedMemorySize, SMEM_BYTES);

    // 1) CSR build + W rearrange (all rounds)
    zero_counts_kernel<<<(N_NODES + 255) / 256, 256>>>();
    hist_kernel<<<(N_EDGES + 255) / 256, 256>>>(eidx);
    scan_kernel<<<1, 1024>>>();
    fill_kernel<<<(N_EDGES + 255) / 256, 256>>>(eidx);
    wcat_kernel<<<(ROUNDS * S_DIM * 2 * S_DIM + 255) / 256, 256>>>(W_msg);

    // 2) input net: state = relu(x @ W_in + b_in)   [25000,128]@[128,256]
    {
        dim3 grid(S_DIM / TBN, (N_NODES + TBM - 1) / TBM);
        gemm_tf32_kernel<<<grid, 256, SMEM_BYTES>>>(x, W_in, b_in, state, N_NODES, S_DIM, F_DIM, 1);
    }

    // 3) message rounds
    for (int r = 0; r < ROUNDS; r++) {
        {
            dim3 grid((2 * S_DIM) / TBN, (N_NODES + TBM - 1) / TBM);
            gemm_tf32_kernel<<<grid, 256, SMEM_BYTES>>>(
                state, Wcat + (size_t)r * S_DIM * 2 * S_DIM, nullptr, P,
                N_NODES, 2 * S_DIM, S_DIM, 0);
        }
        aggregate_kernel<<<(N_NODES + 7) / 8, 256>>>(b_msg + (size_t)r * S_DIM);
    }

    // 4) output net: out = state @ W_out + b_out   [25000,256]@[256,64]  (fp32 path)
    {
        dim3 grid(L_DIM / BN, (N_NODES + BM - 1) / BM);
        gemm_kernel<<<grid, 256>>>(state, W_out, b_out, out, N_NODES, L_DIM, S_DIM, 0);
    }
}

// round 4
// speedup vs baseline: 2.1827x; 1.0630x over previous
#include <cuda_runtime.h>
#include <cuda_fp16.h>

// Problem constants (match reference setup_inputs)
#define N_NODES 25000
#define N_EDGES 400000
#define F_DIM   128
#define S_DIM   256
#define L_DIM   64
#define ROUNDS  4

// ---------------- scratch (static __device__, no allocations) ----------------
__device__ float  g_state[N_NODES * S_DIM];                 // 25.6 MB
__device__ __half g_Psrc[N_NODES * S_DIM];                  // 12.8 MB (fp16 src-half of P)
__device__ float  g_Pdst[N_NODES * S_DIM];                  // 25.6 MB (fp32 dst-half of P)
__device__ float  g_Wcat[ROUNDS * S_DIM * 2 * S_DIM];       // 2 MB (all rounds)
__device__ int    g_cnt[N_NODES];
__device__ int    g_cur[N_NODES];
__device__ int    g_rowptr[N_NODES + 1];
__device__ int    g_esrc[N_EDGES];

// ---------------- CSR build (counting sort by dest) ----------------
__global__ void zero_counts_kernel() {
    int i = blockIdx.x * blockDim.x + threadIdx.x;
    if (i < N_NODES) { g_cnt[i] = 0; g_cur[i] = 0; }
}

__global__ void hist_kernel(const int* __restrict__ edge_index) {
    int e = blockIdx.x * blockDim.x + threadIdx.x;
    if (e < N_EDGES) {
        int d = edge_index[N_EDGES + e];
        atomicAdd(&g_cnt[d], 1);
    }
}

// single-block exclusive scan of g_cnt -> g_rowptr (shfl-based, 1024 threads)
__global__ void scan_kernel() {
    __shared__ int warp_tot[32];
    const int CH = (N_NODES + 1023) / 1024;   // 25
    int t = threadIdx.x;
    int lane = t & 31, wid = t >> 5;
    int base = t * CH;
    int sum = 0;
#pragma unroll
    for (int i = 0; i < CH; i++) {
        int idx = base + i;
        if (idx < N_NODES) sum += g_cnt[idx];
    }
    int v = sum;
#pragma unroll
    for (int off = 1; off < 32; off <<= 1) {
        int n = __shfl_up_sync(0xffffffff, v, off);
        if (lane >= off) v += n;
    }
    if (lane == 31) warp_tot[wid] = v;
    __syncthreads();
    if (wid == 0) {
        int w = warp_tot[lane];
#pragma unroll
        for (int off = 1; off < 32; off <<= 1) {
            int n = __shfl_up_sync(0xffffffff, w, off);
            if (lane >= off) w += n;
        }
        warp_tot[lane] = w;
    }
    __syncthreads();
    int excl = v - sum + (wid > 0 ? warp_tot[wid - 1] : 0);
    int run = excl;
#pragma unroll
    for (int i = 0; i < CH; i++) {
        int idx = base + i;
        if (idx < N_NODES) { g_rowptr[idx] = run; run += g_cnt[idx]; }
    }
    if (t == 1023) g_rowptr[N_NODES] = run;
}

__global__ void fill_kernel(const int* __restrict__ edge_index) {
    int e = blockIdx.x * blockDim.x + threadIdx.x;
    if (e < N_EDGES) {
        int s = edge_index[e];
        int d = edge_index[N_EDGES + e];
        int pos = g_rowptr[d] + atomicAdd(&g_cur[d], 1);
        g_esrc[pos] = s;
    }
}

// ---------------- W rearrange for ALL rounds in one launch ----------------
// Wcat[r][k][j] = (j<S)? W[r][k][j] : W[r][S+k][j-S]
__global__ void wcat_kernel(const float* __restrict__ W) {
    int i = blockIdx.x * blockDim.x + threadIdx.x;
    if (i >= ROUNDS * S_DIM * 2 * S_DIM) return;
    int r = i / (S_DIM * 2 * S_DIM);
    int rem = i % (S_DIM * 2 * S_DIM);
    int k = rem / (2 * S_DIM);
    int j = rem % (2 * S_DIM);
    const float* Wr = W + (size_t)r * 2 * S_DIM * S_DIM;
    g_Wcat[i] = (j < S_DIM) ? Wr[k * S_DIM + j] : Wr[(S_DIM + k) * S_DIM + (j - S_DIM)];
}

// ---------------- TF32 tensor-core GEMM, double-buffered ----------------
// BM=128, BN=128, BK=32, 256 threads (8 warps), warp tile 64x32 via m16n8k8.
// Handles N not multiple of 128 via column guards.
// split mode (Csrc != nullptr): cols [0,256) -> fp16 Csrc, cols [256,512) -> fp32 Cdst.
#define TBM 128
#define TBN 128
#define TBK 32
#define A_PAD 133
#define B_PAD 132
#define A_BUF_ELEMS (TBK * A_PAD)
#define B_BUF_ELEMS (TBK * B_PAD)
#define SMEM_BYTES ((2 * A_BUF_ELEMS + 2 * B_BUF_ELEMS) * 4)

__device__ __forceinline__ unsigned f2tf32(float f) {
    unsigned r;
    asm("cvt.rna.tf32.f32 %0, %1;" : "=r"(r) : "f"(f));
    return r;
}

__global__ __launch_bounds__(256, 2) void gemm_tf32_kernel(
    const float* __restrict__ A, const float* __restrict__ B,
    const float* __restrict__ bias, float* __restrict__ C,
    __half* __restrict__ Csrc, float* __restrict__ Cdst,
    int M, int N, int K, int do_relu)
{
    extern __shared__ unsigned smem[];
    unsigned* As = smem;                       // [2][TBK][A_PAD]
    unsigned* Bs = smem + 2 * A_BUF_ELEMS;     // [2][TBK][B_PAD]

    int tid  = threadIdx.x;
    int lane = tid & 31;
    int wid  = tid >> 5;
    int warp_m = wid & 1;
    int warp_n = wid >> 1;
    int m_warp = warp_m * 64;
    int n_warp = warp_n * 32;
    int g   = lane >> 2;
    int tig = lane & 3;

    int row_blk = blockIdx.y * TBM;
    int col_blk = blockIdx.x * TBN;

    float c[4][4][4];
#pragma unroll
    for (int mt = 0; mt < 4; mt++)
#pragma unroll
        for (int nt = 0; nt < 4; nt++)
#pragma unroll
            for (int i = 0; i < 4; i++) c[mt][nt][i] = 0.f;

    int a_kt  = tid & 7;
    int a_row = tid >> 3;
    int b_nt  = tid & 31;
    int b_kr  = tid >> 5;

    int nk = K / TBK;
    float4 av[4], bv4[4];
    bool bcol_ok = (col_blk + b_nt * 4) < N;

    // prologue: load tile 0
#pragma unroll
    for (int p = 0; p < 4; p++) {
        int grow = row_blk + p * 32 + a_row;
        av[p] = make_float4(0.f, 0.f, 0.f, 0.f);
        if (grow < M) av[p] = *(const float4*)&A[(size_t)grow * K + a_kt * 4];
        bv4[p] = make_float4(0.f, 0.f, 0.f, 0.f);
        if (bcol_ok) bv4[p] = *(const float4*)&B[(size_t)(p * 8 + b_kr) * N + col_blk + b_nt * 4];
    }

    for (int t = 0; t < nk; t++) {
        int cur = t & 1;
        unsigned* Ac = As + cur * A_BUF_ELEMS;
        unsigned* Bc = Bs + cur * B_BUF_ELEMS;

#pragma unroll
        for (int p = 0; p < 4; p++) {
            int row = p * 32 + a_row;
            Ac[(a_kt * 4 + 0) * A_PAD + row] = f2tf32(av[p].x);
            Ac[(a_kt * 4 + 1) * A_PAD + row] = f2tf32(av[p].y);
            Ac[(a_kt * 4 + 2) * A_PAD + row] = f2tf32(av[p].z);
            Ac[(a_kt * 4 + 3) * A_PAD + row] = f2tf32(av[p].w);
            int kk = p * 8 + b_kr;
            uint4 w;
            w.x = f2tf32(bv4[p].x); w.y = f2tf32(bv4[p].y);
            w.z = f2tf32(bv4[p].z); w.w = f2tf32(bv4[p].w);
            *(uint4*)&Bc[kk * B_PAD + b_nt * 4] = w;
        }
        __syncthreads();

        if (t + 1 < nk) {
            int k0 = (t + 1) * TBK;
#pragma unroll
            for (int p = 0; p < 4; p++) {
                int grow = row_blk + p * 32 + a_row;
                av[p] = make_float4(0.f, 0.f, 0.f, 0.f);
                if (grow < M) av[p] = *(const float4*)&A[(size_t)grow * K + k0 + a_kt * 4];
                bv4[p] = make_float4(0.f, 0.f, 0.f, 0.f);
                if (bcol_ok) bv4[p] = *(const float4*)&B[(size_t)(k0 + p * 8 + b_kr) * N + col_blk + b_nt * 4];
            }
        }

#pragma unroll
        for (int ks = 0; ks < TBK; ks += 8) {
            unsigned af[4][4], bf[4][2];
#pragma unroll
            for (int mt = 0; mt < 4; mt++) {
                int mb = m_warp + mt * 16;
                af[mt][0] = Ac[(ks + tig) * A_PAD + mb + g];
                af[mt][1] = Ac[(ks + tig) * A_PAD + mb + g + 8];
                af[mt][2] = Ac[(ks + tig + 4) * A_PAD + mb + g];
                af[mt][3] = Ac[(ks + tig + 4) * A_PAD + mb + g + 8];
            }
#pragma unroll
            for (int nt = 0; nt < 4; nt++) {
                int nb = n_warp + nt * 8;
                bf[nt][0] = Bc[(ks + tig) * B_PAD + nb + g];
                bf[nt][1] = Bc[(ks + tig + 4) * B_PAD + nb + g];
            }
#pragma unroll
            for (int mt = 0; mt < 4; mt++)
#pragma unroll
                for (int nt = 0; nt < 4; nt++) {
                    asm volatile(
                        "mma.sync.aligned.m16n8k8.row.col.f32.tf32.tf32.f32 "
                        "{%0,%1,%2,%3}, {%4,%5,%6,%7}, {%8,%9}, {%0,%1,%2,%3};"
                        : "+f"(c[mt][nt][0]), "+f"(c[mt][nt][1]),
                          "+f"(c[mt][nt][2]), "+f"(c[mt][nt][3])
                        : "r"(af[mt][0]), "r"(af[mt][1]), "r"(af[mt][2]), "r"(af[mt][3]),
                          "r"(bf[nt][0]), "r"(bf[nt][1]));
                }
        }
        __syncthreads();
    }

    // epilogue
#pragma unroll
    for (int mt = 0; mt < 4; mt++) {
#pragma unroll
        for (int nt = 0; nt < 4; nt++) {
            int col = col_blk + n_warp + nt * 8 + tig * 2;
            if (col >= N) continue;
            float bv0 = bias ? bias[col] : 0.f;
            float bv1 = bias ? bias[col + 1] : 0.f;
            int r0 = row_blk + m_warp + mt * 16 + g;
            int r1 = r0 + 8;
            float2 o0, o1;
            o0.x = c[mt][nt][0] + bv0; o0.y = c[mt][nt][1] + bv1;
            o1.x = c[mt][nt][2] + bv0; o1.y = c[mt][nt][3] + bv1;
            if (do_relu) {
                o0.x = fmaxf(o0.x, 0.f); o0.y = fmaxf(o0.y, 0.f);
                o1.x = fmaxf(o1.x, 0.f); o1.y = fmaxf(o1.y, 0.f);
            }
            if (Csrc) {
                // split mode: cols [0,S) -> fp16 Psrc, cols [S,2S) -> fp32 Pdst
                if (col < S_DIM) {
                    __half2* H = (__half2*)Csrc;
                    if (r0 < M) H[((size_t)r0 * S_DIM + col) >> 1] = __floats2half2_rn(o0.x, o0.y);
                    if (r1 < M) H[((size_t)r1 * S_DIM + col) >> 1] = __floats2half2_rn(o1.x, o1.y);
                } else {
                    int cc = col - S_DIM;
                    if (r0 < M) *(float2*)&Cdst[(size_t)r0 * S_DIM + cc] = o0;
                    if (r1 < M) *(float2*)&Cdst[(size_t)r1 * S_DIM + cc] = o1;
                }
            } else {
                if (r0 < M) *(float2*)&C[(size_t)r0 * N + col] = o0;
                if (r1 < M) *(float2*)&C[(size_t)r1 * N + col] = o1;
            }
        }
    }
}

// ---------------- per-node aggregation, fp16 src gathers, unroll x4 ----------------
// state[n] += sum_e relu(h2f(Psrc[src_e]) + Pdst[n] + b); one warp per node.
// Each lane owns 8 columns: Psrc read = one uint4 (8 halfs), base = 2 float4.
__global__ __launch_bounds__(256) void aggregate_kernel(const float* __restrict__ b_msg_r) {
    int warp = blockIdx.x * 8 + (threadIdx.x >> 5);
    if (warp >= N_NODES) return;
    int lane = threadIdx.x & 31;

    const float4* Pd = (const float4*)(g_Pdst + (size_t)warp * S_DIM);
    const float4* Bb = (const float4*)b_msg_r;

    float4 base0 = Pd[lane * 2 + 0];
    float4 base1 = Pd[lane * 2 + 1];
    float4 bb0 = Bb[lane * 2 + 0];
    float4 bb1 = Bb[lane * 2 + 1];
    base0.x += bb0.x; base0.y += bb0.y; base0.z += bb0.z; base0.w += bb0.w;
    base1.x += bb1.x; base1.y += bb1.y; base1.z += bb1.z; base1.w += bb1.w;

    float4 acc0 = make_float4(0.f, 0.f, 0.f, 0.f);
    float4 acc1 = make_float4(0.f, 0.f, 0.f, 0.f);

    const uint4* Ph = (const uint4*)g_Psrc;   // one uint4 = 8 halfs; row = S_DIM/8 = 32 uint4
    int s = g_rowptr[warp];
    int e = g_rowptr[warp + 1];

#define ACC_EDGE(q)                                                          \
    do {                                                                     \
        __half2 h0 = *(__half2*)&(q).x;                                      \
        __half2 h1 = *(__half2*)&(q).y;                                      \
        __half2 h2 = *(__half2*)&(q).z;                                      \
        __half2 h3 = *(__half2*)&(q).w;                                      \
        float2 f0 = __half22float2(h0);                                      \
        float2 f1 = __half22float2(h1);                                      \
        float2 f2 = __half22float2(h2);                                      \
        float2 f3 = __half22float2(h3);                                      \
        acc0.x += fmaxf(f0.x + base0.x, 0.f);                                \
        acc0.y += fmaxf(f0.y + base0.y, 0.f);                                \
        acc0.z += fmaxf(f1.x + base0.z, 0.f);                                \
        acc0.w += fmaxf(f1.y + base0.w, 0.f);                                \
        acc1.x += fmaxf(f2.x + base1.x, 0.f);                                \
        acc1.y += fmaxf(f2.y + base1.y, 0.f);                                \
        acc1.z += fmaxf(f3.x + base1.z, 0.f);                                \
        acc1.w += fmaxf(f3.y + base1.w, 0.f);                                \
    } while (0)

    int i = s;
    for (; i + 4 <= e; i += 4) {
        int s0 = g_esrc[i];
        int s1 = g_esrc[i + 1];
        int s2 = g_esrc[i + 2];
        int s3 = g_esrc[i + 3];
        uint4 q0 = Ph[(size_t)s0 * 32 + lane];
        uint4 q1 = Ph[(size_t)s1 * 32 + lane];
        uint4 q2 = Ph[(size_t)s2 * 32 + lane];
        uint4 q3 = Ph[(size_t)s3 * 32 + lane];
        ACC_EDGE(q0); ACC_EDGE(q1); ACC_EDGE(q2); ACC_EDGE(q3);
    }
    for (; i < e; i++) {
        int s0 = g_esrc[i];
        uint4 q0 = Ph[(size_t)s0 * 32 + lane];
        ACC_EDGE(q0);
    }
#undef ACC_EDGE

    float4* st = (float4*)(g_state + (size_t)warp * S_DIM);
    float4 s0 = st[lane * 2 + 0];
    float4 s1 = st[lane * 2 + 1];
    s0.x += acc0.x; s0.y += acc0.y; s0.z += acc0.z; s0.w += acc0.w;
    s1.x += acc1.x; s1.y += acc1.y; s1.z += acc1.z; s1.w += acc1.w;
    st[lane * 2 + 0] = s0;
    st[lane * 2 + 1] = s1;
}

// ---------------- launch ----------------
extern "C" void kernel_launch(void* const* d_in, const int* in_sizes, int n_in,
                              void* d_out, int out_size)
{
    const float* x        = (const float*)d_in[0];
    const int*   eidx     = (const int*)d_in[1];
    // d_in[2] = batch (unused by reference)
    const float* W_in     = (const float*)d_in[3];
    const float* b_in     = (const float*)d_in[4];
    const float* W_msg    = (const float*)d_in[5];   // [ROUNDS, 2S, S]
    const float* b_msg    = (const float*)d_in[6];   // [ROUNDS, S]
    const float* W_out    = (const float*)d_in[7];
    const float* b_out    = (const float*)d_in[8];
    float*       out      = (float*)d_out;

    float*  state; cudaGetSymbolAddress((void**)&state, g_state);
    __half* Psrc;  cudaGetSymbolAddress((void**)&Psrc,  g_Psrc);
    float*  Pdst;  cudaGetSymbolAddress((void**)&Pdst,  g_Pdst);
    float*  Wcat;  cudaGetSymbolAddress((void**)&Wcat,  g_Wcat);

    cudaFuncSetAttribute(gemm_tf32_kernel,
                         cudaFuncAttributeMaxDynamicSharedMemorySize, SMEM_BYTES);

    // 1) CSR build + W rearrange (all rounds)
    zero_counts_kernel<<<(N_NODES + 255) / 256, 256>>>();
    hist_kernel<<<(N_EDGES + 255) / 256, 256>>>(eidx);
    scan_kernel<<<1, 1024>>>();
    fill_kernel<<<(N_EDGES + 255) / 256, 256>>>(eidx);
    wcat_kernel<<<(ROUNDS * S_DIM * 2 * S_DIM + 255) / 256, 256>>>(W_msg);

    // 2) input net: state = relu(x @ W_in + b_in)   [25000,128]@[128,256]
    {
        dim3 grid(S_DIM / TBN, (N_NODES + TBM - 1) / TBM);
        gemm_tf32_kernel<<<grid, 256, SMEM_BYTES>>>(
            x, W_in, b_in, state, nullptr, nullptr, N_NODES, S_DIM, F_DIM, 1);
    }

    // 3) message rounds
    for (int r = 0; r < ROUNDS; r++) {
        {
            dim3 grid((2 * S_DIM) / TBN, (N_NODES + TBM - 1) / TBM);
            gemm_tf32_kernel<<<grid, 256, SMEM_BYTES>>>(
                state, Wcat + (size_t)r * S_DIM * 2 * S_DIM, nullptr, nullptr,
                Psrc, Pdst, N_NODES, 2 * S_DIM, S_DIM, 0);
        }
        aggregate_kernel<<<(N_NODES + 7) / 8, 256>>>(b_msg + (size_t)r * S_DIM);
    }

    // 4) output net: out = state @ W_out + b_out   [25000,256]@[256,64]  (tf32, col-guarded)
    {
        dim3 grid(1, (N_NODES + TBM - 1) / TBM);
        gemm_tf32_kernel<<<grid, 256, SMEM_BYTES>>>(
            state, W_out, b_out, out, nullptr, nullptr, N_NODES, L_DIM, S_DIM, 0);
    }
}

// round 5
// speedup vs baseline: 2.8762x; 1.3177x over previous
#include <cuda_runtime.h>
#include <cuda_fp16.h>

// Problem constants (match reference setup_inputs)
#define N_NODES 25000
#define N_EDGES 400000
#define F_DIM   128
#define S_DIM   256
#define L_DIM   64
#define ROUNDS  4

// ---------------- scratch (static __device__, no allocations) ----------------
__device__ float  g_state[N_NODES * S_DIM];                 // 25.6 MB (fp32 master)
__device__ __half g_state_h[N_NODES * S_DIM];               // 12.8 MB (fp16 GEMM operand)
__device__ __half g_xh[N_NODES * F_DIM];                    // 6.4 MB
__device__ __half g_Psrc[N_NODES * S_DIM];                  // 12.8 MB
__device__ float  g_Pdst[N_NODES * S_DIM];                  // 25.6 MB
__device__ __half g_WinT[S_DIM * F_DIM];                    // [N=256][K=128]
__device__ __half g_WcatT[ROUNDS * 2 * S_DIM * S_DIM];      // [r][N=512][K=256], 1 MB
__device__ __half g_WoutT[L_DIM * S_DIM];                   // [N=64][K=256]
__device__ int    g_cnt[N_NODES];
__device__ int    g_cur[N_NODES];
__device__ int    g_rowptr[N_NODES + 1];
__device__ int    g_esrc[N_EDGES];

// ---------------- CSR build (counting sort by dest) ----------------
__global__ void zero_counts_kernel() {
    int i = blockIdx.x * blockDim.x + threadIdx.x;
    if (i < N_NODES) { g_cnt[i] = 0; g_cur[i] = 0; }
}

__global__ void hist_kernel(const int* __restrict__ edge_index) {
    int e = blockIdx.x * blockDim.x + threadIdx.x;
    if (e < N_EDGES) {
        int d = edge_index[N_EDGES + e];
        atomicAdd(&g_cnt[d], 1);
    }
}

__global__ void scan_kernel() {
    __shared__ int warp_tot[32];
    const int CH = (N_NODES + 1023) / 1024;   // 25
    int t = threadIdx.x;
    int lane = t & 31, wid = t >> 5;
    int base = t * CH;
    int sum = 0;
#pragma unroll
    for (int i = 0; i < CH; i++) {
        int idx = base + i;
        if (idx < N_NODES) sum += g_cnt[idx];
    }
    int v = sum;
#pragma unroll
    for (int off = 1; off < 32; off <<= 1) {
        int n = __shfl_up_sync(0xffffffff, v, off);
        if (lane >= off) v += n;
    }
    if (lane == 31) warp_tot[wid] = v;
    __syncthreads();
    if (wid == 0) {
        int w = warp_tot[lane];
#pragma unroll
        for (int off = 1; off < 32; off <<= 1) {
            int n = __shfl_up_sync(0xffffffff, w, off);
            if (lane >= off) w += n;
        }
        warp_tot[lane] = w;
    }
    __syncthreads();
    int excl = v - sum + (wid > 0 ? warp_tot[wid - 1] : 0);
    int run = excl;
#pragma unroll
    for (int i = 0; i < CH; i++) {
        int idx = base + i;
        if (idx < N_NODES) { g_rowptr[idx] = run; run += g_cnt[idx]; }
    }
    if (t == 1023) g_rowptr[N_NODES] = run;
}

__global__ void fill_kernel(const int* __restrict__ edge_index) {
    int e = blockIdx.x * blockDim.x + threadIdx.x;
    if (e < N_EDGES) {
        int s = edge_index[e];
        int d = edge_index[N_EDGES + e];
        int pos = g_rowptr[d] + atomicAdd(&g_cur[d], 1);
        g_esrc[pos] = s;
    }
}

// ---------------- fp16 operand prep ----------------
__global__ void conv_x_kernel(const float* __restrict__ x) {
    int i = blockIdx.x * blockDim.x + threadIdx.x;
    if (i < N_NODES * F_DIM) g_xh[i] = __float2half(x[i]);
}

// builds W_inT [256][128], WcatT [r][512][256], W_outT [64][256], all fp16
__global__ void prep_weights_kernel(const float* __restrict__ W_in,
                                    const float* __restrict__ W_msg,
                                    const float* __restrict__ W_out) {
    const int N1 = S_DIM * F_DIM;
    const int N2 = ROUNDS * 2 * S_DIM * S_DIM;
    const int N3 = L_DIM * S_DIM;
    int i = blockIdx.x * blockDim.x + threadIdx.x;
    if (i < N1) {
        int j = i / F_DIM, k = i % F_DIM;
        g_WinT[i] = __float2half(W_in[k * S_DIM + j]);
    } else if (i < N1 + N2) {
        int t = i - N1;
        int r = t / (2 * S_DIM * S_DIM);
        int rem = t % (2 * S_DIM * S_DIM);
        int j = rem / S_DIM;       // 0..511
        int k = rem % S_DIM;
        const float* Wr = W_msg + (size_t)r * 2 * S_DIM * S_DIM;
        float v = (j < S_DIM) ? Wr[k * S_DIM + j] : Wr[(S_DIM + k) * S_DIM + (j - S_DIM)];
        g_WcatT[t] = __float2half(v);
    } else if (i < N1 + N2 + N3) {
        int t = i - N1 - N2;
        int j = t / S_DIM, k = t % S_DIM;
        g_WoutT[t] = __float2half(W_out[k * L_DIM + j]);
    }
}

// ---------------- fp16 tensor-core GEMM, double-buffered ----------------
// C[M,N] = act(A[M,K] @ B^T  + bias), B given as [N][K] fp16 (pre-transposed).
// BM=128, BN=128, BK=32, 256 threads (8 warps), warp tile 64x32 via m16n8k16.
// split mode (Csrc != nullptr): cols [0,256) -> fp16 Psrc, cols [256,512) -> fp32 Pdst.
// Ch != nullptr: also write fp16 copy of C.
#define TBM 128
#define TBN 128
#define TBK 32
#define KP  56                               // padded halfs per smem row
#define TILE_ELEMS (128 * KP)                // per buffer (A or B)
#define SMEM_BYTES (4 * TILE_ELEMS * 2)      // 2 bufs x (A+B) x 2B

__global__ __launch_bounds__(256, 2) void gemm_f16_kernel(
    const __half* __restrict__ A, const __half* __restrict__ B,
    const float* __restrict__ bias, float* __restrict__ C,
    __half* __restrict__ Ch, __half* __restrict__ Csrc, float* __restrict__ Cdst,
    int M, int N, int K, int do_relu)
{
    extern __shared__ __half sm[];
    __half* As = sm;                     // [2][128][KP]
    __half* Bs = sm + 2 * TILE_ELEMS;    // [2][128][KP]

    int tid  = threadIdx.x;
    int lane = tid & 31;
    int wid  = tid >> 5;
    int warp_m = wid & 1;
    int warp_n = wid >> 1;
    int m_warp = warp_m * 64;
    int n_warp = warp_n * 32;
    int g   = lane >> 2;
    int tig = lane & 3;

    int row_blk = blockIdx.y * TBM;
    int col_blk = blockIdx.x * TBN;

    float c[4][4][4];
#pragma unroll
    for (int mt = 0; mt < 4; mt++)
#pragma unroll
        for (int nt = 0; nt < 4; nt++)
#pragma unroll
            for (int i = 0; i < 4; i++) c[mt][nt][i] = 0.f;

    // global loads: uint4 = 8 halfs; 4 chunks per 32-half row; 64 rows/pass, 2 passes
    int kt  = tid & 3;
    int trow = tid >> 2;

    int nk = K / TBK;
    uint4 av[2], bv[2];
    const uint4 zero4 = make_uint4(0, 0, 0, 0);

    // prologue: tile 0
#pragma unroll
    for (int p = 0; p < 2; p++) {
        int ar = row_blk + p * 64 + trow;
        av[p] = (ar < M) ? *(const uint4*)&A[(size_t)ar * K + kt * 8] : zero4;
        int br = col_blk + p * 64 + trow;
        bv[p] = (br < N) ? *(const uint4*)&B[(size_t)br * K + kt * 8] : zero4;
    }

    for (int t = 0; t < nk; t++) {
        int cur = t & 1;
        __half* Ac = As + cur * TILE_ELEMS;
        __half* Bc = Bs + cur * TILE_ELEMS;

#pragma unroll
        for (int p = 0; p < 2; p++) {
            int row = p * 64 + trow;
            *(uint4*)&Ac[row * KP + kt * 8] = av[p];
            *(uint4*)&Bc[row * KP + kt * 8] = bv[p];
        }
        __syncthreads();

        if (t + 1 < nk) {
            int k0 = (t + 1) * TBK;
#pragma unroll
            for (int p = 0; p < 2; p++) {
                int ar = row_blk + p * 64 + trow;
                av[p] = (ar < M) ? *(const uint4*)&A[(size_t)ar * K + k0 + kt * 8] : zero4;
                int br = col_blk + p * 64 + trow;
                bv[p] = (br < N) ? *(const uint4*)&B[(size_t)br * K + k0 + kt * 8] : zero4;
            }
        }

#pragma unroll
        for (int ks = 0; ks < TBK; ks += 16) {
            unsigned af[4][4], bf[4][2];
#pragma unroll
            for (int mt = 0; mt < 4; mt++) {
                int mb = m_warp + mt * 16;
                af[mt][0] = *(unsigned*)&Ac[(mb + g) * KP + ks + tig * 2];
                af[mt][1] = *(unsigned*)&Ac[(mb + g + 8) * KP + ks + tig * 2];
                af[mt][2] = *(unsigned*)&Ac[(mb + g) * KP + ks + tig * 2 + 8];
                af[mt][3] = *(unsigned*)&Ac[(mb + g + 8) * KP + ks + tig * 2 + 8];
            }
#pragma unroll
            for (int nt = 0; nt < 4; nt++) {
                int nb = n_warp + nt * 8;
                bf[nt][0] = *(unsigned*)&Bc[(nb + g) * KP + ks + tig * 2];
                bf[nt][1] = *(unsigned*)&Bc[(nb + g) * KP + ks + tig * 2 + 8];
            }
#pragma unroll
            for (int mt = 0; mt < 4; mt++)
#pragma unroll
                for (int nt = 0; nt < 4; nt++) {
                    asm volatile(
                        "mma.sync.aligned.m16n8k16.row.col.f32.f16.f16.f32 "
                        "{%0,%1,%2,%3}, {%4,%5,%6,%7}, {%8,%9}, {%0,%1,%2,%3};"
                        : "+f"(c[mt][nt][0]), "+f"(c[mt][nt][1]),
                          "+f"(c[mt][nt][2]), "+f"(c[mt][nt][3])
                        : "r"(af[mt][0]), "r"(af[mt][1]), "r"(af[mt][2]), "r"(af[mt][3]),
                          "r"(bf[nt][0]), "r"(bf[nt][1]));
                }
        }
        __syncthreads();
    }

    // epilogue
#pragma unroll
    for (int mt = 0; mt < 4; mt++) {
#pragma unroll
        for (int nt = 0; nt < 4; nt++) {
            int col = col_blk + n_warp + nt * 8 + tig * 2;
            if (col >= N) continue;
            float bv0 = bias ? bias[col] : 0.f;
            float bv1 = bias ? bias[col + 1] : 0.f;
            int r0 = row_blk + m_warp + mt * 16 + g;
            int r1 = r0 + 8;
            float2 o0, o1;
            o0.x = c[mt][nt][0] + bv0; o0.y = c[mt][nt][1] + bv1;
            o1.x = c[mt][nt][2] + bv0; o1.y = c[mt][nt][3] + bv1;
            if (do_relu) {
                o0.x = fmaxf(o0.x, 0.f); o0.y = fmaxf(o0.y, 0.f);
                o1.x = fmaxf(o1.x, 0.f); o1.y = fmaxf(o1.y, 0.f);
            }
            if (Csrc) {
                // split mode: cols [0,S) -> fp16 Psrc, cols [S,2S) -> fp32 Pdst
                if (col < S_DIM) {
                    __half2* H = (__half2*)Csrc;
                    if (r0 < M) H[((size_t)r0 * S_DIM + col) >> 1] = __floats2half2_rn(o0.x, o0.y);
                    if (r1 < M) H[((size_t)r1 * S_DIM + col) >> 1] = __floats2half2_rn(o1.x, o1.y);
                } else {
                    int cc = col - S_DIM;
                    if (r0 < M) *(float2*)&Cdst[(size_t)r0 * S_DIM + cc] = o0;
                    if (r1 < M) *(float2*)&Cdst[(size_t)r1 * S_DIM + cc] = o1;
                }
            } else {
                if (r0 < M) {
                    *(float2*)&C[(size_t)r0 * N + col] = o0;
                    if (Ch) *(__half2*)&Ch[(size_t)r0 * N + col] = __floats2half2_rn(o0.x, o0.y);
                }
                if (r1 < M) {
                    *(float2*)&C[(size_t)r1 * N + col] = o1;
                    if (Ch) *(__half2*)&Ch[(size_t)r1 * N + col] = __floats2half2_rn(o1.x, o1.y);
                }
            }
        }
    }
}

// ---------------- per-node aggregation, fp16 src gathers, unroll x4 ----------------
// state[n] += sum_e relu(h2f(Psrc[src_e]) + Pdst[n] + b); writes fp32 + fp16 state.
__global__ __launch_bounds__(256) void aggregate_kernel(const float* __restrict__ b_msg_r) {
    int warp = blockIdx.x * 8 + (threadIdx.x >> 5);
    if (warp >= N_NODES) return;
    int lane = threadIdx.x & 31;

    const float4* Pd = (const float4*)(g_Pdst + (size_t)warp * S_DIM);
    const float4* Bb = (const float4*)b_msg_r;

    float4 base0 = Pd[lane * 2 + 0];
    float4 base1 = Pd[lane * 2 + 1];
    float4 bb0 = Bb[lane * 2 + 0];
    float4 bb1 = Bb[lane * 2 + 1];
    base0.x += bb0.x; base0.y += bb0.y; base0.z += bb0.z; base0.w += bb0.w;
    base1.x += bb1.x; base1.y += bb1.y; base1.z += bb1.z; base1.w += bb1.w;

    float4 acc0 = make_float4(0.f, 0.f, 0.f, 0.f);
    float4 acc1 = make_float4(0.f, 0.f, 0.f, 0.f);

    const uint4* Ph = (const uint4*)g_Psrc;   // row = 32 uint4
    int s = g_rowptr[warp];
    int e = g_rowptr[warp + 1];

#define ACC_EDGE(q)                                                          \
    do {                                                                     \
        float2 f0 = __half22float2(*(__half2*)&(q).x);                       \
        float2 f1 = __half22float2(*(__half2*)&(q).y);                       \
        float2 f2 = __half22float2(*(__half2*)&(q).z);                       \
        float2 f3 = __half22float2(*(__half2*)&(q).w);                       \
        acc0.x += fmaxf(f0.x + base0.x, 0.f);                                \
        acc0.y += fmaxf(f0.y + base0.y, 0.f);                                \
        acc0.z += fmaxf(f1.x + base0.z, 0.f);                                \
        acc0.w += fmaxf(f1.y + base0.w, 0.f);                                \
        acc1.x += fmaxf(f2.x + base1.x, 0.f);                                \
        acc1.y += fmaxf(f2.y + base1.y, 0.f);                                \
        acc1.z += fmaxf(f3.x + base1.z, 0.f);                                \
        acc1.w += fmaxf(f3.y + base1.w, 0.f);                                \
    } while (0)

    int i = s;
    for (; i + 4 <= e; i += 4) {
        int s0 = g_esrc[i];
        int s1 = g_esrc[i + 1];
        int s2 = g_esrc[i + 2];
        int s3 = g_esrc[i + 3];
        uint4 q0 = Ph[(size_t)s0 * 32 + lane];
        uint4 q1 = Ph[(size_t)s1 * 32 + lane];
        uint4 q2 = Ph[(size_t)s2 * 32 + lane];
        uint4 q3 = Ph[(size_t)s3 * 32 + lane];
        ACC_EDGE(q0); ACC_EDGE(q1); ACC_EDGE(q2); ACC_EDGE(q3);
    }
    for (; i < e; i++) {
        int s0 = g_esrc[i];
        uint4 q0 = Ph[(size_t)s0 * 32 + lane];
        ACC_EDGE(q0);
    }
#undef ACC_EDGE

    float4* st = (float4*)(g_state + (size_t)warp * S_DIM);
    float4 s0 = st[lane * 2 + 0];
    float4 s1 = st[lane * 2 + 1];
    s0.x += acc0.x; s0.y += acc0.y; s0.z += acc0.z; s0.w += acc0.w;
    s1.x += acc1.x; s1.y += acc1.y; s1.z += acc1.z; s1.w += acc1.w;
    st[lane * 2 + 0] = s0;
    st[lane * 2 + 1] = s1;

    // fp16 shadow for the next GEMM
    __half2 h0 = __floats2half2_rn(s0.x, s0.y);
    __half2 h1 = __floats2half2_rn(s0.z, s0.w);
    __half2 h2 = __floats2half2_rn(s1.x, s1.y);
    __half2 h3 = __floats2half2_rn(s1.z, s1.w);
    uint4 pk;
    pk.x = *(unsigned*)&h0; pk.y = *(unsigned*)&h1;
    pk.z = *(unsigned*)&h2; pk.w = *(unsigned*)&h3;
    *(uint4*)&g_state_h[(size_t)warp * S_DIM + lane * 8] = pk;
}

// ---------------- launch ----------------
extern "C" void kernel_launch(void* const* d_in, const int* in_sizes, int n_in,
                              void* d_out, int out_size)
{
    const float* x        = (const float*)d_in[0];
    const int*   eidx     = (const int*)d_in[1];
    // d_in[2] = batch (unused by reference)
    const float* W_in     = (const float*)d_in[3];
    const float* b_in     = (const float*)d_in[4];
    const float* W_msg    = (const float*)d_in[5];   // [ROUNDS, 2S, S]
    const float* b_msg    = (const float*)d_in[6];   // [ROUNDS, S]
    const float* W_out    = (const float*)d_in[7];
    const float* b_out    = (const float*)d_in[8];
    float*       out      = (float*)d_out;

    float*  state;   cudaGetSymbolAddress((void**)&state,   g_state);
    __half* state_h; cudaGetSymbolAddress((void**)&state_h, g_state_h);
    __half* xh;      cudaGetSymbolAddress((void**)&xh,      g_xh);
    __half* Psrc;    cudaGetSymbolAddress((void**)&Psrc,    g_Psrc);
    float*  Pdst;    cudaGetSymbolAddress((void**)&Pdst,    g_Pdst);
    __half* WinT;    cudaGetSymbolAddress((void**)&WinT,    g_WinT);
    __half* WcatT;   cudaGetSymbolAddress((void**)&WcatT,   g_WcatT);
    __half* WoutT;   cudaGetSymbolAddress((void**)&WoutT,   g_WoutT);

    cudaFuncSetAttribute(gemm_f16_kernel,
                         cudaFuncAttributeMaxDynamicSharedMemorySize, SMEM_BYTES);

    // 1) CSR build + fp16 operand prep
    zero_counts_kernel<<<(N_NODES + 255) / 256, 256>>>();
    hist_kernel<<<(N_EDGES + 255) / 256, 256>>>(eidx);
    scan_kernel<<<1, 1024>>>();
    fill_kernel<<<(N_EDGES + 255) / 256, 256>>>(eidx);
    conv_x_kernel<<<(N_NODES * F_DIM + 255) / 256, 256>>>(x);
    {
        int tot = S_DIM * F_DIM + ROUNDS * 2 * S_DIM * S_DIM + L_DIM * S_DIM;
        prep_weights_kernel<<<(tot + 255) / 256, 256>>>(W_in, W_msg, W_out);
    }

    // 2) input net: state = relu(x @ W_in + b_in), also fp16 shadow
    {
        dim3 grid(S_DIM / TBN, (N_NODES + TBM - 1) / TBM);
        gemm_f16_kernel<<<grid, 256, SMEM_BYTES>>>(
            xh, WinT, b_in, state, state_h, nullptr, nullptr,
            N_NODES, S_DIM, F_DIM, 1);
    }

    // 3) message rounds
    for (int r = 0; r < ROUNDS; r++) {
        {
            dim3 grid((2 * S_DIM) / TBN, (N_NODES + TBM - 1) / TBM);
            gemm_f16_kernel<<<grid, 256, SMEM_BYTES>>>(
                state_h, WcatT + (size_t)r * 2 * S_DIM * S_DIM, nullptr, nullptr,
                nullptr, Psrc, Pdst, N_NODES, 2 * S_DIM, S_DIM, 0);
        }
        aggregate_kernel<<<(N_NODES + 7) / 8, 256>>>(b_msg + (size_t)r * S_DIM);
    }

    // 4) output net: out = state @ W_out + b_out
    {
        dim3 grid(1, (N_NODES + TBM - 1) / TBM);
        gemm_f16_kernel<<<grid, 256, SMEM_BYTES>>>(
            state_h, WoutT, b_out, out, nullptr, nullptr, nullptr,
            N_NODES, L_DIM, S_DIM, 0);
    }
}